// round 1
// baseline (speedup 1.0000x reference)
#include <cuda_runtime.h>
#include <cuda_bf16.h>
#include <math.h>

// Problem constants (fixed by the reference): n=100, h=16, w=16, f_in=8, f_out=16
#define N_NODES 100
#define PIX 256            // h*w
#define FIN 8
#define FOUT 16
#define ALPHA 0.2f

// Scratch (device globals; allocation-free per harness rules)
__device__ __align__(16) float g_Wh[N_NODES * PIX * FOUT];        // [j][pixel][c]  1.6MB
__device__ float g_D[N_NODES * 32];                               // [i][r*2+dy]    r in [0,16), dy in {0,1}
__device__ __align__(16) float g_att[N_NODES * N_NODES * FOUT];   // [i][j][c]      640KB
__device__ __align__(16) float g_part[2][N_NODES * PIX * FOUT];   // j-half partials

// ---------------------------------------------------------------------------
// Kernel 1: Wh = x @ W  and  D[i,r,dy] = sum_{x,c} Wh[i,r,x,c] * a[dy*256+x*16+c]
// grid 100 (node i), block 256 (pixel p = y*16+x)
// ---------------------------------------------------------------------------
__global__ __launch_bounds__(256) void k_wh_d(const float* __restrict__ x,
                                              const float* __restrict__ W,
                                              const float* __restrict__ a)
{
    __shared__ float W_s[FIN * FOUT];   // 128
    __shared__ float a_s[512];

    const int i = blockIdx.x;
    const int p = threadIdx.x;

    if (p < FIN * FOUT) W_s[p] = W[p];
    a_s[p]       = a[p];
    a_s[p + 256] = a[p + 256];
    __syncthreads();

    // load x[i, p, 0..7]
    const float4* xp = reinterpret_cast<const float4*>(x) + (size_t)(i * PIX + p) * 2;
    float4 x0 = xp[0];
    float4 x1 = xp[1];
    float xv[8] = {x0.x, x0.y, x0.z, x0.w, x1.x, x1.y, x1.z, x1.w};

    float wh[FOUT];
#pragma unroll
    for (int c = 0; c < FOUT; ++c) {
        float s = 0.f;
#pragma unroll
        for (int k = 0; k < FIN; ++k) s += xv[k] * W_s[k * FOUT + c];
        wh[c] = s;
    }

    // store Wh
    float4* whp = reinterpret_cast<float4*>(g_Wh) + (size_t)(i * PIX + p) * 4;
    whp[0] = make_float4(wh[0],  wh[1],  wh[2],  wh[3]);
    whp[1] = make_float4(wh[4],  wh[5],  wh[6],  wh[7]);
    whp[2] = make_float4(wh[8],  wh[9],  wh[10], wh[11]);
    whp[3] = make_float4(wh[12], wh[13], wh[14], wh[15]);

    // partial D for this pixel's row y, column xx
    const int xx = p & 15;
    float pd0 = 0.f, pd1 = 0.f;
#pragma unroll
    for (int c = 0; c < FOUT; ++c) {
        pd0 += wh[c] * a_s[xx * 16 + c];
        pd1 += wh[c] * a_s[256 + xx * 16 + c];
    }
    // reduce over xx within the 16 consecutive threads of the same row y
#pragma unroll
    for (int off = 8; off >= 1; off >>= 1) {
        pd0 += __shfl_xor_sync(0xffffffffu, pd0, off, 16);
        pd1 += __shfl_xor_sync(0xffffffffu, pd1, off, 16);
    }
    if (xx == 0) {
        const int y = p >> 4;
        g_D[i * 32 + 2 * y]     = pd0;
        g_D[i * 32 + 2 * y + 1] = pd1;
    }
}

// ---------------------------------------------------------------------------
// Kernel 2: e -> leakyrelu -> mask -> softmax over j -> g_att[i][j][c]
// grid 100 (i), block 512: warp index = channel c (16 warps), lane handles j strided 32
// ---------------------------------------------------------------------------
__global__ __launch_bounds__(512) void k_att(const int* __restrict__ adj)
{
    __shared__ float D_i[32];

    const int i   = blockIdx.x;
    const int tid = threadIdx.x;
    const int c   = tid >> 5;    // 0..15
    const int l   = tid & 31;

    if (tid < 32) D_i[tid] = g_D[i * 32 + tid];
    __syncthreads();

    float ev[4];
    float mx = -3.4e38f;
#pragma unroll
    for (int t = 0; t < 4; ++t) {
        const int j = l + t * 32;
        if (j < N_NODES) {
            float e;
            if (c < 8) {
                const int b = 16 * j + 2 * c;
                e = D_i[(b / 100) * 2] + D_i[((b + 1) / 100) * 2 + 1];
            } else {
                const int r = 2 * c - 16;
                e = g_D[j * 32 + 2 * r] + g_D[j * 32 + 2 * (r + 1) + 1];
            }
            e = (e > 0.f) ? e : ALPHA * e;                 // leaky relu
            e = (adj[i * N_NODES + j] > 0) ? e : -9e15f;   // mask
            ev[t] = e;
            mx = fmaxf(mx, e);
        } else {
            ev[t] = -3.4e38f;
        }
    }
#pragma unroll
    for (int off = 16; off >= 1; off >>= 1)
        mx = fmaxf(mx, __shfl_xor_sync(0xffffffffu, mx, off));

    float s = 0.f;
#pragma unroll
    for (int t = 0; t < 4; ++t) {
        const int j = l + t * 32;
        if (j < N_NODES) {
            ev[t] = expf(ev[t] - mx);
            s += ev[t];
        }
    }
#pragma unroll
    for (int off = 16; off >= 1; off >>= 1)
        s += __shfl_xor_sync(0xffffffffu, s, off);

    const float inv = 1.0f / s;
#pragma unroll
    for (int t = 0; t < 4; ++t) {
        const int j = l + t * 32;
        if (j < N_NODES)
            g_att[(size_t)i * (N_NODES * FOUT) + j * FOUT + c] = ev[t] * inv;
    }
}

// ---------------------------------------------------------------------------
// Kernel 3: h_prime partials.
// grid (20 i-tiles of 5, 8 pixel-tiles of 32, 2 j-halves of 50), block 128:
//   warp = c-group (4 channels), lane = pixel-in-tile.
// att slice staged in smem (warp-uniform broadcast reads), Wh streamed float4.
// ---------------------------------------------------------------------------
#define TI 5
#define JR 50
__global__ __launch_bounds__(128) void k_hprime()
{
    __shared__ float att_s[TI * JR * FOUT];   // 16000 B, layout [ii][j][c]

    const int tid = threadIdx.x;
    const int cg  = tid >> 5;                 // 0..3  (warp id)
    const int i0  = blockIdx.x * TI;
    const int p0  = blockIdx.y * 32;
    const int jh  = blockIdx.z;
    const int j0  = jh * JR;

    // stage att slice: TI*JR*16 floats = 1000 float4
    {
        float4* dst = reinterpret_cast<float4*>(att_s);
        const float4* src = reinterpret_cast<const float4*>(g_att);
        for (int q = tid; q < TI * JR * 4; q += 128) {
            const int ii = q / (JR * 4);
            const int r  = q % (JR * 4);
            const int j  = r >> 2;
            const int c4 = r & 3;
            dst[q] = src[(size_t)((i0 + ii) * N_NODES + (j0 + j)) * 4 + c4];
        }
    }
    __syncthreads();

    const int pixel = p0 + (tid & 31);

    float4 acc[TI];
#pragma unroll
    for (int ii = 0; ii < TI; ++ii) acc[ii] = make_float4(0.f, 0.f, 0.f, 0.f);

    const float4* wh4 = reinterpret_cast<const float4*>(g_Wh);
    const float4* as4 = reinterpret_cast<const float4*>(att_s);

    for (int j = 0; j < JR; ++j) {
        const float4 whv = wh4[(size_t)((j0 + j) * PIX + pixel) * 4 + cg];
#pragma unroll
        for (int ii = 0; ii < TI; ++ii) {
            const float4 at = as4[(ii * JR + j) * 4 + cg];   // warp-uniform -> broadcast
            acc[ii].x += at.x * whv.x;
            acc[ii].y += at.y * whv.y;
            acc[ii].z += at.z * whv.z;
            acc[ii].w += at.w * whv.w;
        }
    }

    float4* dst = reinterpret_cast<float4*>(g_part[jh]);
#pragma unroll
    for (int ii = 0; ii < TI; ++ii)
        dst[(size_t)((i0 + ii) * PIX + pixel) * 4 + cg] = acc[ii];
}

// ---------------------------------------------------------------------------
// Kernel 4: out = part0 + part1
// ---------------------------------------------------------------------------
__global__ __launch_bounds__(256) void k_combine(float* __restrict__ out)
{
    const int q = blockIdx.x * 256 + threadIdx.x;   // 102400 float4
    const float4* p0 = reinterpret_cast<const float4*>(g_part[0]);
    const float4* p1 = reinterpret_cast<const float4*>(g_part[1]);
    float4 a = p0[q];
    float4 b = p1[q];
    reinterpret_cast<float4*>(out)[q] =
        make_float4(a.x + b.x, a.y + b.y, a.z + b.z, a.w + b.w);
}

// ---------------------------------------------------------------------------
extern "C" void kernel_launch(void* const* d_in, const int* in_sizes, int n_in,
                              void* d_out, int out_size)
{
    const float* x   = (const float*)d_in[0];   // (100,16,16,8)
    const int*   adj = (const int*)d_in[1];     // (100,100)
    const float* W   = (const float*)d_in[2];   // (8,16)
    const float* a   = (const float*)d_in[3];   // (512,1)
    float* out = (float*)d_out;                 // (100,16,16,16)

    k_wh_d<<<N_NODES, 256>>>(x, W, a);
    k_att<<<N_NODES, 512>>>(adj);
    dim3 g3(N_NODES / TI, PIX / 32, 2);
    k_hprime<<<g3, 128>>>();
    k_combine<<<(N_NODES * PIX * FOUT) / (4 * 256), 256>>>(out);
}